// round 15
// baseline (speedup 1.0000x reference)
#include <cuda_runtime.h>
#include <cuda_bf16.h>

#define BB 8
#define LL 4096
#define DD 1024
#define CC 128
#define SLICE 32
#define MAXSL 256                 // slice slots per batch (>= L/32 + C guaranteed)

// Only cross-block state: arrival counters (zero-init; finalizer self-cleans)
// and the partial-sum scratch.
__device__ int    g_arrive[BB][CC];
__device__ float4 g_part[BB][MAXSL][DD / 4];   // 8 MB

__device__ __forceinline__ int atomic_add_acq_rel(int* p, int v) {
    int old;
    asm volatile("atom.add.acq_rel.gpu.s32 %0, [%1], %2;"
                 : "=r"(old) : "l"(p), "r"(v) : "memory");
    return old;
}

// Cold path: deterministic fixed-order reduction of a chunk's slice partials.
__device__ __noinline__ void finalize_multi(int b, int c, int t,
                                            int first_sl, int nsl, int cnt,
                                            float4* __restrict__ mp) {
    float4 acc = make_float4(0.f, 0.f, 0.f, 0.f);
    for (int i = 0; i < nsl; i++) {
        float4 v = g_part[b][first_sl + i][t];
        acc.x += v.x; acc.y += v.y; acc.z += v.z; acc.w += v.w;
    }
    const float inv = 1.0f / (float)cnt;
    acc.x *= inv; acc.y *= inv; acc.z *= inv; acc.w *= inv;
    mp[t] = acc;
}

// ---------------------------------------------------------------------------
// Single kernel, grid = dim3(MAXSL, BB) = 2048 blocks, 256 threads.
// Block (sl, b): redundantly computes the per-batch scan from boundaries
// (16 KB, L2-hot after wave 1), derives its OWN slice, streams it, finalizes
// via arrival counters. sl >= nsl_total blocks zero empty/invalid chunks.
// No cross-block waiting anywhere. 8 CTAs/SM to hide the prologue latency.
// ---------------------------------------------------------------------------
__global__ void __launch_bounds__(256, 8) chunk_selfscan_kernel(
        const float* __restrict__ x,
        const float* __restrict__ boundaries,
        float* __restrict__ means,
        float* __restrict__ cnts_out,
        int write_cnts) {
    const int t    = threadIdx.x;       // 0..255
    const int lane = t & 31;
    const int wid  = t >> 5;            // 0..7
    const int sl   = blockIdx.x;        // 0..MAXSL-1
    const int b    = blockIdx.y;        // 0..BB-1

    __shared__ int wsum[8], wexcl[8], pos[CC + 1], snb;
    __shared__ int csum[4], cexcl[4], snsl;
    __shared__ int s_meta[6];           // {s, e, chunk, first_sl, nsl, cnt}
    __shared__ int s_last;

    // ---- phase 1: boundary flags (16 tokens/thread) + ordered compaction ----
    const float* bp = boundaries + (size_t)b * LL;
    const int base = t * 16;
    unsigned flags = 0;
    {
        const float4* bp4 = reinterpret_cast<const float4*>(bp + base);
#pragma unroll
        for (int q = 0; q < 4; q++) {
            float4 v = bp4[q];
            if (v.x > 0.5f) flags |= 1u << (q * 4 + 0);
            if (v.y > 0.5f) flags |= 1u << (q * 4 + 1);
            if (v.z > 0.5f) flags |= 1u << (q * 4 + 2);
            if (v.w > 0.5f) flags |= 1u << (q * 4 + 3);
        }
    }
    const int cnt_t = __popc(flags);

    int incl = cnt_t;
#pragma unroll
    for (int d = 1; d < 32; d <<= 1) {
        int v = __shfl_up_sync(0xFFFFFFFFu, incl, d);
        if (lane >= d) incl += v;
    }
    if (lane == 31) wsum[wid] = incl;
    __syncthreads();

    if (t < 8) {
        int v = wsum[t];
        int iv = v;
#pragma unroll
        for (int d = 1; d < 8; d <<= 1) {
            int u = __shfl_up_sync(0x000000FFu, iv, d);
            if (t >= d) iv += u;
        }
        wexcl[t] = iv - v;
        if (t == 7) snb = iv;
    }
    __syncthreads();

    {
        int idx = wexcl[wid] + (incl - cnt_t);
        unsigned f = flags;
        while (f) {
            int i = __ffs(f) - 1;
            f &= f - 1;
            if (idx <= CC) pos[idx] = base + i;
            idx++;
        }
    }
    __syncthreads();

    const int nb = snb;
    const int valid = nb < CC ? nb : CC;

    // ---- phase 2: chunk ranges + slice-count prefix; locate OUR slice ----
    int s0 = 0, e0 = 0, len = 0, nsl = 0;
    if (t < CC && t < valid) {
        s0 = pos[t];
        e0 = (t + 1 < nb) ? pos[t + 1] : LL;
        len = e0 - s0;
        nsl = (len + SLICE - 1) / SLICE;
    }

    int cincl = nsl;
#pragma unroll
    for (int d = 1; d < 32; d <<= 1) {
        int v = __shfl_up_sync(0xFFFFFFFFu, cincl, d);
        if (lane >= d) cincl += v;
    }
    if (t < CC && lane == 31) csum[wid] = cincl;
    __syncthreads();

    if (t < 4) {
        int v = csum[t];
        int iv = v;
#pragma unroll
        for (int d = 1; d < 4; d <<= 1) {
            int u = __shfl_up_sync(0x0000000Fu, iv, d);
            if (t >= d) iv += u;
        }
        cexcl[t] = iv - v;
        if (t == 3) snsl = iv;
    }
    __syncthreads();

    const int nsl_total = snsl;

    if (t < CC && t < valid) {
        const int soff = cexcl[wid] + (cincl - nsl);
        if (soff <= sl && sl < soff + nsl) {      // exactly one thread matches
            const int ss = s0 + (sl - soff) * SLICE;
            const int ee = (ss + SLICE) < e0 ? (ss + SLICE) : e0;
            s_meta[0] = ss; s_meta[1] = ee; s_meta[2] = t;
            s_meta[3] = soff; s_meta[4] = nsl; s_meta[5] = len;
        }
    }
    // cnts output: one designated block per batch (runs even if nsl_total==0)
    if (write_cnts && sl == 0 && t < CC) {
        cnts_out[b * CC + t] = (float)len;        // len==0 for t >= valid
    }
    __syncthreads();

    // ---- idle slice slots take zeroing duty for empty/invalid chunks ----
    // capacity: MAXSL - nsl_total >= CC - valid  (since nsl_total <= 128 + valid)
    if (sl >= nsl_total) {
        const int c = valid + (sl - nsl_total);   // empty chunks are [valid, CC)
        if (c < CC) {
            const float4 z = make_float4(0.f, 0.f, 0.f, 0.f);
            reinterpret_cast<float4*>(
                means + ((size_t)b * CC + c) * DD)[t] = z;
        }
        return;
    }

    // ---- stream our slice (validated round-13 loop) ----
    const int ss     = s_meta[0];
    const int ee     = s_meta[1];
    const int c      = s_meta[2];
    const int first  = s_meta[3];
    const int nsl_c  = s_meta[4];
    const int cnt_c  = s_meta[5];
    const int n      = ee - ss;

    // 32-bit offset math (fits: 8*4096*1024 < 2^31)
    const float4* __restrict__ xp =
        reinterpret_cast<const float4*>(x) + (b * LL + ss) * (DD / 4) + t;

    float4 a0 = make_float4(0.f, 0.f, 0.f, 0.f);
    float4 a1 = make_float4(0.f, 0.f, 0.f, 0.f);

    if (n == SLICE) {
#pragma unroll
        for (int i = 0; i < SLICE; i += 2) {
            float4 v0 = xp[(i + 0) * (DD / 4)];
            float4 v1 = xp[(i + 1) * (DD / 4)];
            a0.x += v0.x; a0.y += v0.y; a0.z += v0.z; a0.w += v0.w;
            a1.x += v1.x; a1.y += v1.y; a1.z += v1.z; a1.w += v1.w;
        }
    } else {
        int i = 0;
#pragma unroll 4
        for (; i + 1 < n; i += 2) {
            float4 v0 = xp[(i + 0) * (DD / 4)];
            float4 v1 = xp[(i + 1) * (DD / 4)];
            a0.x += v0.x; a0.y += v0.y; a0.z += v0.z; a0.w += v0.w;
            a1.x += v1.x; a1.y += v1.y; a1.z += v1.z; a1.w += v1.w;
        }
        if (i < n) {
            float4 v0 = xp[i * (DD / 4)];
            a0.x += v0.x; a0.y += v0.y; a0.z += v0.z; a0.w += v0.w;
        }
    }
    a0.x += a1.x; a0.y += a1.y; a0.z += a1.z; a0.w += a1.w;

    float4* __restrict__ mp =
        reinterpret_cast<float4*>(means + ((size_t)b * CC + c) * DD);

    if (nsl_c == 1) {
        const float inv = 1.0f / (float)n;
        a0.x *= inv; a0.y *= inv; a0.z *= inv; a0.w *= inv;
        mp[t] = a0;
        return;
    }

    // multi-slice: publish partial, last-arriving block finalizes (fixed order)
    g_part[b][sl][t] = a0;
    __syncthreads();                  // all partial stores before t0's release
    if (t == 0) {
        s_last = (atomic_add_acq_rel(&g_arrive[b][c], 1) == nsl_c - 1);
    }
    __syncthreads();                  // distribute acquire
    if (s_last) {
        finalize_multi(b, c, t, first, nsl_c, cnt_c, mp);
        if (t == 0) g_arrive[b][c] = 0;   // self-clean for graph replay
    }
}

extern "C" void kernel_launch(void* const* d_in, const int* in_sizes, int n_in,
                              void* d_out, int out_size) {
    const float* x = nullptr;
    const float* boundaries = nullptr;
    for (int i = 0; i < n_in; i++) {
        if (in_sizes[i] == BB * LL * DD) x = (const float*)d_in[i];
        else if (in_sizes[i] == BB * LL) boundaries = (const float*)d_in[i];
    }

    float* out = (float*)d_out;
    const int means_elems = BB * CC * DD;
    const int write_cnts = (out_size > means_elems) ? 1 : 0;

    chunk_selfscan_kernel<<<dim3(MAXSL, BB), 256>>>(
        x, boundaries, out, out + means_elems, write_cnts);
}

// round 16
// speedup vs baseline: 1.0308x; 1.0308x over previous
#include <cuda_runtime.h>
#include <cuda_bf16.h>

#define BB 8
#define LL 4096
#define DD 1024
#define CC 128
#define SLICE 32
#define MAXSL 256                 // slice slots per batch (>= L/32 + C guaranteed)

// Only cross-block state: arrival counters (zero-init; finalizer self-cleans)
// and the partial-sum scratch.
__device__ int    g_arrive[BB][CC];
__device__ float4 g_part[BB][MAXSL][DD / 4];   // 8 MB

__device__ __forceinline__ int atomic_add_acq_rel(int* p, int v) {
    int old;
    asm volatile("atom.add.acq_rel.gpu.s32 %0, [%1], %2;"
                 : "=r"(old) : "l"(p), "r"(v) : "memory");
    return old;
}
__device__ __forceinline__ void prefetch_l2(const void* p) {
    asm volatile("prefetch.global.L2 [%0];" :: "l"(p));
}

// Cold path: deterministic fixed-order reduction of a chunk's slice partials.
__device__ __noinline__ void finalize_multi(int b, int c, int t,
                                            int first_sl, int nsl, int cnt,
                                            float4* __restrict__ mp) {
    float4 acc = make_float4(0.f, 0.f, 0.f, 0.f);
    for (int i = 0; i < nsl; i++) {
        float4 v = g_part[b][first_sl + i][t];
        acc.x += v.x; acc.y += v.y; acc.z += v.z; acc.w += v.w;
    }
    const float inv = 1.0f / (float)cnt;
    acc.x *= inv; acc.y *= inv; acc.z *= inv; acc.w *= inv;
    mp[t] = acc;
}

// ---------------------------------------------------------------------------
// Single kernel, grid = BB*MAXSL = 2048 blocks, 256 threads (round-13 champion
// + static L2 prefetch of each block's 64KB stripe of x issued at cycle 0).
// Block (b, sl): redundantly computes the per-batch scan from boundaries
// (16 KB, L2-hot), derives its OWN slice, streams it, finalizes via arrival
// counters. sl >= nsl_total blocks zero the empty/invalid chunks. No
// cross-block waiting anywhere.
// ---------------------------------------------------------------------------
__global__ void __launch_bounds__(256) chunk_selfscan_kernel(
        const float* __restrict__ x,
        const float* __restrict__ boundaries,
        float* __restrict__ means,
        float* __restrict__ cnts_out,
        int write_cnts) {
    const int t    = threadIdx.x;       // 0..255
    const int lane = t & 31;
    const int wid  = t >> 5;            // 0..7
    const int b    = blockIdx.x >> 8;   // / MAXSL
    const int sl   = blockIdx.x & (MAXSL - 1);

    // ---- static L2 prefetch: this block's 16-token (64KB) stripe of x.
    // Addresses are scan-independent -> DRAM busy while the prologue runs.
    // 2048 blocks x 64KB = full 128MB coverage, spatially correlated with the
    // tokens this block will actually stream.
    {
        const char* pre = reinterpret_cast<const char*>(x) +
                          (size_t)blockIdx.x * (16u * DD * 4u) + (size_t)t * 256u;
        prefetch_l2(pre);
        prefetch_l2(pre + 128);
    }

    __shared__ int wsum[8], wexcl[8], pos[CC + 1], snb;
    __shared__ int csum[4], cexcl[4], snsl;
    __shared__ int s_meta[6];           // {s, e, chunk, first_sl, nsl, cnt}
    __shared__ int s_last;

    // ---- phase 1: boundary flags (16 tokens/thread) + ordered compaction ----
    const float* bp = boundaries + (size_t)b * LL;
    const int base = t * 16;
    unsigned flags = 0;
    {
        const float4* bp4 = reinterpret_cast<const float4*>(bp + base);
#pragma unroll
        for (int q = 0; q < 4; q++) {
            float4 v = bp4[q];
            if (v.x > 0.5f) flags |= 1u << (q * 4 + 0);
            if (v.y > 0.5f) flags |= 1u << (q * 4 + 1);
            if (v.z > 0.5f) flags |= 1u << (q * 4 + 2);
            if (v.w > 0.5f) flags |= 1u << (q * 4 + 3);
        }
    }
    const int cnt_t = __popc(flags);

    int incl = cnt_t;
#pragma unroll
    for (int d = 1; d < 32; d <<= 1) {
        int v = __shfl_up_sync(0xFFFFFFFFu, incl, d);
        if (lane >= d) incl += v;
    }
    if (lane == 31) wsum[wid] = incl;
    __syncthreads();

    if (t < 8) {
        int v = wsum[t];
        int iv = v;
#pragma unroll
        for (int d = 1; d < 8; d <<= 1) {
            int u = __shfl_up_sync(0x000000FFu, iv, d);
            if (t >= d) iv += u;
        }
        wexcl[t] = iv - v;
        if (t == 7) snb = iv;
    }
    __syncthreads();

    {
        int idx = wexcl[wid] + (incl - cnt_t);
        unsigned f = flags;
        while (f) {
            int i = __ffs(f) - 1;
            f &= f - 1;
            if (idx <= CC) pos[idx] = base + i;
            idx++;
        }
    }
    __syncthreads();

    const int nb = snb;
    const int valid = nb < CC ? nb : CC;

    // ---- phase 2: chunk ranges + slice-count prefix; locate OUR slice ----
    int s0 = 0, e0 = 0, len = 0, nsl = 0;
    if (t < CC && t < valid) {
        s0 = pos[t];
        e0 = (t + 1 < nb) ? pos[t + 1] : LL;
        len = e0 - s0;
        nsl = (len + SLICE - 1) / SLICE;
    }

    int cincl = nsl;
#pragma unroll
    for (int d = 1; d < 32; d <<= 1) {
        int v = __shfl_up_sync(0xFFFFFFFFu, cincl, d);
        if (lane >= d) cincl += v;
    }
    if (t < CC && lane == 31) csum[wid] = cincl;
    __syncthreads();

    if (t < 4) {
        int v = csum[t];
        int iv = v;
#pragma unroll
        for (int d = 1; d < 4; d <<= 1) {
            int u = __shfl_up_sync(0x0000000Fu, iv, d);
            if (t >= d) iv += u;
        }
        cexcl[t] = iv - v;
        if (t == 3) snsl = iv;
    }
    __syncthreads();

    const int nsl_total = snsl;

    if (t < CC && t < valid) {
        const int soff = cexcl[wid] + (cincl - nsl);
        if (soff <= sl && sl < soff + nsl) {      // exactly one thread matches
            const int ss = s0 + (sl - soff) * SLICE;
            const int ee = (ss + SLICE) < e0 ? (ss + SLICE) : e0;
            s_meta[0] = ss; s_meta[1] = ee; s_meta[2] = t;
            s_meta[3] = soff; s_meta[4] = nsl; s_meta[5] = len;
        }
    }
    // cnts output: one designated block per batch (runs even if nsl_total==0)
    if (write_cnts && sl == 0 && t < CC) {
        cnts_out[b * CC + t] = (float)len;        // len==0 for t >= valid
    }
    __syncthreads();

    // ---- idle slice slots take zeroing duty for empty/invalid chunks ----
    if (sl >= nsl_total) {
        const int c = valid + (sl - nsl_total);   // empty chunks are [valid, CC)
        if (c < CC) {
            const float4 z = make_float4(0.f, 0.f, 0.f, 0.f);
            reinterpret_cast<float4*>(
                means + ((size_t)b * CC + c) * DD)[t] = z;
        }
        return;
    }

    // ---- stream our slice (round-13 validated loop) ----
    const int ss     = s_meta[0];
    const int ee     = s_meta[1];
    const int c      = s_meta[2];
    const int first  = s_meta[3];
    const int nsl_c  = s_meta[4];
    const int cnt_c  = s_meta[5];
    const int n      = ee - ss;

    // 32-bit offset math (fits: 8*4096*1024 < 2^31)
    const float4* __restrict__ xp =
        reinterpret_cast<const float4*>(x) + (b * LL + ss) * (DD / 4) + t;

    float4 a0 = make_float4(0.f, 0.f, 0.f, 0.f);
    float4 a1 = make_float4(0.f, 0.f, 0.f, 0.f);

    if (n == SLICE) {
#pragma unroll
        for (int i = 0; i < SLICE; i += 2) {
            float4 v0 = xp[(i + 0) * (DD / 4)];
            float4 v1 = xp[(i + 1) * (DD / 4)];
            a0.x += v0.x; a0.y += v0.y; a0.z += v0.z; a0.w += v0.w;
            a1.x += v1.x; a1.y += v1.y; a1.z += v1.z; a1.w += v1.w;
        }
    } else {
        int i = 0;
#pragma unroll 4
        for (; i + 1 < n; i += 2) {
            float4 v0 = xp[(i + 0) * (DD / 4)];
            float4 v1 = xp[(i + 1) * (DD / 4)];
            a0.x += v0.x; a0.y += v0.y; a0.z += v0.z; a0.w += v0.w;
            a1.x += v1.x; a1.y += v1.y; a1.z += v1.z; a1.w += v1.w;
        }
        if (i < n) {
            float4 v0 = xp[i * (DD / 4)];
            a0.x += v0.x; a0.y += v0.y; a0.z += v0.z; a0.w += v0.w;
        }
    }
    a0.x += a1.x; a0.y += a1.y; a0.z += a1.z; a0.w += a1.w;

    float4* __restrict__ mp =
        reinterpret_cast<float4*>(means + ((size_t)b * CC + c) * DD);

    if (nsl_c == 1) {
        const float inv = 1.0f / (float)n;
        a0.x *= inv; a0.y *= inv; a0.z *= inv; a0.w *= inv;
        mp[t] = a0;
        return;
    }

    // multi-slice: publish partial, last-arriving block finalizes (fixed order)
    g_part[b][sl][t] = a0;
    __syncthreads();                  // all partial stores before t0's release
    if (t == 0) {
        s_last = (atomic_add_acq_rel(&g_arrive[b][c], 1) == nsl_c - 1);
    }
    __syncthreads();                  // distribute acquire
    if (s_last) {
        finalize_multi(b, c, t, first, nsl_c, cnt_c, mp);
        if (t == 0) g_arrive[b][c] = 0;   // self-clean for graph replay
    }
}

extern "C" void kernel_launch(void* const* d_in, const int* in_sizes, int n_in,
                              void* d_out, int out_size) {
    const float* x = nullptr;
    const float* boundaries = nullptr;
    for (int i = 0; i < n_in; i++) {
        if (in_sizes[i] == BB * LL * DD) x = (const float*)d_in[i];
        else if (in_sizes[i] == BB * LL) boundaries = (const float*)d_in[i];
    }

    float* out = (float*)d_out;
    const int means_elems = BB * CC * DD;
    const int write_cnts = (out_size > means_elems) ? 1 : 0;

    chunk_selfscan_kernel<<<BB * MAXSL, 256>>>(
        x, boundaries, out, out + means_elems, write_cnts);
}

// round 17
// speedup vs baseline: 1.0380x; 1.0070x over previous
#include <cuda_runtime.h>
#include <cuda_bf16.h>

#define BB 8
#define LL 4096
#define DD 1024
#define CC 128
#define SLICE 32
#define MAXSL 256                 // slice slots per batch (>= L/32 + C guaranteed)

// Only cross-block state: arrival counters (zero-init; finalizer self-cleans)
// and the partial-sum scratch.
__device__ int    g_arrive[BB][CC];
__device__ float4 g_part[BB][MAXSL][DD / 4];   // 8 MB

__device__ __forceinline__ int atomic_add_acq_rel(int* p, int v) {
    int old;
    asm volatile("atom.add.acq_rel.gpu.s32 %0, [%1], %2;"
                 : "=r"(old) : "l"(p), "r"(v) : "memory");
    return old;
}
__device__ __forceinline__ void prefetch_l2(const void* p) {
    asm volatile("prefetch.global.L2 [%0];" :: "l"(p));
}
// Evict-first stores/loads: keep dead-on-arrival output + scratch traffic from
// evicting prefetched x lines out of L2.
__device__ __forceinline__ void st_cs_f4(float4* p, float4 v) {
    asm volatile("st.global.cs.v4.f32 [%0], {%1, %2, %3, %4};"
                 :: "l"(p), "f"(v.x), "f"(v.y), "f"(v.z), "f"(v.w) : "memory");
}
__device__ __forceinline__ float4 ld_cs_f4(const float4* p) {
    float4 v;
    asm volatile("ld.global.cs.v4.f32 {%0, %1, %2, %3}, [%4];"
                 : "=f"(v.x), "=f"(v.y), "=f"(v.z), "=f"(v.w) : "l"(p));
    return v;
}

// Cold path: deterministic fixed-order reduction of a chunk's slice partials.
__device__ __noinline__ void finalize_multi(int b, int c, int t,
                                            int first_sl, int nsl, int cnt,
                                            float4* __restrict__ mp) {
    float4 acc = make_float4(0.f, 0.f, 0.f, 0.f);
    for (int i = 0; i < nsl; i++) {
        float4 v = ld_cs_f4(&g_part[b][first_sl + i][t]);
        acc.x += v.x; acc.y += v.y; acc.z += v.z; acc.w += v.w;
    }
    const float inv = 1.0f / (float)cnt;
    acc.x *= inv; acc.y *= inv; acc.z *= inv; acc.w *= inv;
    st_cs_f4(&mp[t], acc);
}

// ---------------------------------------------------------------------------
// Single kernel, grid = BB*MAXSL = 2048 blocks, 256 threads (round-16 champion
// + evict-first policy on all output/scratch traffic).
// Block (b, sl): static L2 prefetch of its x stripe at cycle 0, redundant
// per-batch scan from boundaries (16 KB, L2-hot), derive OWN slice, stream,
// finalize via arrival counters. sl >= nsl_total blocks zero empty chunks.
// No cross-block waiting anywhere.
// ---------------------------------------------------------------------------
__global__ void __launch_bounds__(256) chunk_selfscan_kernel(
        const float* __restrict__ x,
        const float* __restrict__ boundaries,
        float* __restrict__ means,
        float* __restrict__ cnts_out,
        int write_cnts) {
    const int t    = threadIdx.x;       // 0..255
    const int lane = t & 31;
    const int wid  = t >> 5;            // 0..7
    const int b    = blockIdx.x >> 8;   // / MAXSL
    const int sl   = blockIdx.x & (MAXSL - 1);

    // ---- static L2 prefetch: this block's 16-token (64KB) stripe of x.
    {
        const char* pre = reinterpret_cast<const char*>(x) +
                          (size_t)blockIdx.x * (16u * DD * 4u) + (size_t)t * 256u;
        prefetch_l2(pre);
        prefetch_l2(pre + 128);
    }

    __shared__ int wsum[8], wexcl[8], pos[CC + 1], snb;
    __shared__ int csum[4], cexcl[4], snsl;
    __shared__ int s_meta[6];           // {s, e, chunk, first_sl, nsl, cnt}
    __shared__ int s_last;

    // ---- phase 1: boundary flags (16 tokens/thread) + ordered compaction ----
    const float* bp = boundaries + (size_t)b * LL;
    const int base = t * 16;
    unsigned flags = 0;
    {
        const float4* bp4 = reinterpret_cast<const float4*>(bp + base);
#pragma unroll
        for (int q = 0; q < 4; q++) {
            float4 v = bp4[q];
            if (v.x > 0.5f) flags |= 1u << (q * 4 + 0);
            if (v.y > 0.5f) flags |= 1u << (q * 4 + 1);
            if (v.z > 0.5f) flags |= 1u << (q * 4 + 2);
            if (v.w > 0.5f) flags |= 1u << (q * 4 + 3);
        }
    }
    const int cnt_t = __popc(flags);

    int incl = cnt_t;
#pragma unroll
    for (int d = 1; d < 32; d <<= 1) {
        int v = __shfl_up_sync(0xFFFFFFFFu, incl, d);
        if (lane >= d) incl += v;
    }
    if (lane == 31) wsum[wid] = incl;
    __syncthreads();

    if (t < 8) {
        int v = wsum[t];
        int iv = v;
#pragma unroll
        for (int d = 1; d < 8; d <<= 1) {
            int u = __shfl_up_sync(0x000000FFu, iv, d);
            if (t >= d) iv += u;
        }
        wexcl[t] = iv - v;
        if (t == 7) snb = iv;
    }
    __syncthreads();

    {
        int idx = wexcl[wid] + (incl - cnt_t);
        unsigned f = flags;
        while (f) {
            int i = __ffs(f) - 1;
            f &= f - 1;
            if (idx <= CC) pos[idx] = base + i;
            idx++;
        }
    }
    __syncthreads();

    const int nb = snb;
    const int valid = nb < CC ? nb : CC;

    // ---- phase 2: chunk ranges + slice-count prefix; locate OUR slice ----
    int s0 = 0, e0 = 0, len = 0, nsl = 0;
    if (t < CC && t < valid) {
        s0 = pos[t];
        e0 = (t + 1 < nb) ? pos[t + 1] : LL;
        len = e0 - s0;
        nsl = (len + SLICE - 1) / SLICE;
    }

    int cincl = nsl;
#pragma unroll
    for (int d = 1; d < 32; d <<= 1) {
        int v = __shfl_up_sync(0xFFFFFFFFu, cincl, d);
        if (lane >= d) cincl += v;
    }
    if (t < CC && lane == 31) csum[wid] = cincl;
    __syncthreads();

    if (t < 4) {
        int v = csum[t];
        int iv = v;
#pragma unroll
        for (int d = 1; d < 4; d <<= 1) {
            int u = __shfl_up_sync(0x0000000Fu, iv, d);
            if (t >= d) iv += u;
        }
        cexcl[t] = iv - v;
        if (t == 3) snsl = iv;
    }
    __syncthreads();

    const int nsl_total = snsl;

    if (t < CC && t < valid) {
        const int soff = cexcl[wid] + (cincl - nsl);
        if (soff <= sl && sl < soff + nsl) {      // exactly one thread matches
            const int ss = s0 + (sl - soff) * SLICE;
            const int ee = (ss + SLICE) < e0 ? (ss + SLICE) : e0;
            s_meta[0] = ss; s_meta[1] = ee; s_meta[2] = t;
            s_meta[3] = soff; s_meta[4] = nsl; s_meta[5] = len;
        }
    }
    // cnts output: one designated block per batch (runs even if nsl_total==0)
    if (write_cnts && sl == 0 && t < CC) {
        cnts_out[b * CC + t] = (float)len;        // len==0 for t >= valid
    }
    __syncthreads();

    // ---- idle slice slots take zeroing duty for empty/invalid chunks ----
    if (sl >= nsl_total) {
        const int c = valid + (sl - nsl_total);   // empty chunks are [valid, CC)
        if (c < CC) {
            const float4 z = make_float4(0.f, 0.f, 0.f, 0.f);
            st_cs_f4(&reinterpret_cast<float4*>(
                         means + ((size_t)b * CC + c) * DD)[t], z);
        }
        return;
    }

    // ---- stream our slice (round-13 validated loop) ----
    const int ss     = s_meta[0];
    const int ee     = s_meta[1];
    const int c      = s_meta[2];
    const int first  = s_meta[3];
    const int nsl_c  = s_meta[4];
    const int cnt_c  = s_meta[5];
    const int n      = ee - ss;

    // 32-bit offset math (fits: 8*4096*1024 < 2^31)
    const float4* __restrict__ xp =
        reinterpret_cast<const float4*>(x) + (b * LL + ss) * (DD / 4) + t;

    float4 a0 = make_float4(0.f, 0.f, 0.f, 0.f);
    float4 a1 = make_float4(0.f, 0.f, 0.f, 0.f);

    if (n == SLICE) {
#pragma unroll
        for (int i = 0; i < SLICE; i += 2) {
            float4 v0 = xp[(i + 0) * (DD / 4)];
            float4 v1 = xp[(i + 1) * (DD / 4)];
            a0.x += v0.x; a0.y += v0.y; a0.z += v0.z; a0.w += v0.w;
            a1.x += v1.x; a1.y += v1.y; a1.z += v1.z; a1.w += v1.w;
        }
    } else {
        int i = 0;
#pragma unroll 4
        for (; i + 1 < n; i += 2) {
            float4 v0 = xp[(i + 0) * (DD / 4)];
            float4 v1 = xp[(i + 1) * (DD / 4)];
            a0.x += v0.x; a0.y += v0.y; a0.z += v0.z; a0.w += v0.w;
            a1.x += v1.x; a1.y += v1.y; a1.z += v1.z; a1.w += v1.w;
        }
        if (i < n) {
            float4 v0 = xp[i * (DD / 4)];
            a0.x += v0.x; a0.y += v0.y; a0.z += v0.z; a0.w += v0.w;
        }
    }
    a0.x += a1.x; a0.y += a1.y; a0.z += a1.z; a0.w += a1.w;

    float4* __restrict__ mp =
        reinterpret_cast<float4*>(means + ((size_t)b * CC + c) * DD);

    if (nsl_c == 1) {
        const float inv = 1.0f / (float)n;
        a0.x *= inv; a0.y *= inv; a0.z *= inv; a0.w *= inv;
        st_cs_f4(&mp[t], a0);
        return;
    }

    // multi-slice: publish partial, last-arriving block finalizes (fixed order)
    st_cs_f4(&g_part[b][sl][t], a0);
    __syncthreads();                  // all partial stores before t0's release
    if (t == 0) {
        s_last = (atomic_add_acq_rel(&g_arrive[b][c], 1) == nsl_c - 1);
    }
    __syncthreads();                  // distribute acquire
    if (s_last) {
        finalize_multi(b, c, t, first, nsl_c, cnt_c, mp);
        if (t == 0) g_arrive[b][c] = 0;   // self-clean for graph replay
    }
}

extern "C" void kernel_launch(void* const* d_in, const int* in_sizes, int n_in,
                              void* d_out, int out_size) {
    const float* x = nullptr;
    const float* boundaries = nullptr;
    for (int i = 0; i < n_in; i++) {
        if (in_sizes[i] == BB * LL * DD) x = (const float*)d_in[i];
        else if (in_sizes[i] == BB * LL) boundaries = (const float*)d_in[i];
    }

    float* out = (float*)d_out;
    const int means_elems = BB * CC * DD;
    const int write_cnts = (out_size > means_elems) ? 1 : 0;

    chunk_selfscan_kernel<<<BB * MAXSL, 256>>>(
        x, boundaries, out, out + means_elems, write_cnts);
}